// round 14
// baseline (speedup 1.0000x reference)
#include <cuda_runtime.h>
#include <cstdint>

#define SIGMA_INV 10000.0f  // 1 / 1e-4

// factor = 1 - prob = 1 - sigmoid(-d/sigma)*mask = mask ? sigmoid(d/sigma) : 1
__device__ __forceinline__ float blend_factor(float d, int face) {
    float s = __fdividef(1.0f, 1.0f + __expf(-d * SIGMA_INV));
    return (face >= 0) ? s : 1.0f;
}

// Persistent grid-stride version of the R5 scheme: 2 threads per pixel,
// front-batched 2x float4 + 2x int4 streaming loads, 1-shuffle reduce,
// one float4 store per pixel. Grid sized to exactly one wave.
__global__ void __launch_bounds__(256)
self_shader_kernel(const float* __restrict__ zbuf,
                   const float* __restrict__ dists,
                   const int* __restrict__ pix_to_face,
                   float* __restrict__ out,
                   int n_pix) {
    int sub = threadIdx.x & 1;            // which half of K=16
    int stride_pairs = (gridDim.x * blockDim.x) >> 1;   // pixel stride
    int pair0 = (blockIdx.x * blockDim.x + threadIdx.x) >> 1;

    const float4* d4b = reinterpret_cast<const float4*>(dists);
    const int4*   f4b = reinterpret_cast<const int4*>(pix_to_face);
    float4*       o4  = reinterpret_cast<float4*>(out);

    for (int pix = pair0; pix < n_pix; pix += stride_pairs) {
        size_t base = ((size_t)pix << 2) + (sub << 1);

        float4 d0 = __ldcs(d4b + base);
        float4 d1 = __ldcs(d4b + base + 1);
        int4   f0 = __ldcs(f4b + base);
        int4   f1 = __ldcs(f4b + base + 1);
        float  z  = __ldg(&zbuf[(size_t)pix << 4]);  // channel 0 only

        float prod = blend_factor(d0.x, f0.x) * blend_factor(d0.y, f0.y)
                   * blend_factor(d0.z, f0.z) * blend_factor(d0.w, f0.w);
        prod *= blend_factor(d1.x, f1.x) * blend_factor(d1.y, f1.y)
              * blend_factor(d1.z, f1.z) * blend_factor(d1.w, f1.w);

        // combine two halves (lanes 2p, 2p+1 adjacent in warp)
        prod *= __shfl_xor_sync(0xFFFFFFFFu, prod, 1);

        if (sub == 0) {
            __stcs(o4 + pix, make_float4(z, z, z, 1.0f - prod));
        }
    }
}

extern "C" void kernel_launch(void* const* d_in, const int* in_sizes, int n_in,
                              void* d_out, int out_size) {
    const float* zbuf  = (const float*)d_in[0];
    const float* dists = (const float*)d_in[1];
    const int*   p2f   = (const int*)d_in[2];
    float*       out   = (float*)d_out;

    int n_pix = in_sizes[0] / 16;   // N*H*W

    // Exactly one wave: 148 SMs (GB300: 152) x 8 blocks of 256 threads.
    // Use 152 to match GB300's SM count; extra blocks just round-robin.
    int block = 256;
    int grid  = 152 * 8;
    long long needed = ((long long)n_pix * 2 + block - 1) / block;
    if (needed < grid) grid = (int)needed;

    self_shader_kernel<<<grid, block>>>(zbuf, dists, p2f, out, n_pix);
}

// round 15
// speedup vs baseline: 1.0364x; 1.0364x over previous
#include <cuda_runtime.h>
#include <cstdint>

#define SIGMA_INV 10000.0f  // 1 / 1e-4

// factor = 1 - prob = 1 - sigmoid(-d/sigma)*mask = mask ? sigmoid(d/sigma) : 1
__device__ __forceinline__ float blend_factor(float d, int face) {
    float s = __fdividef(1.0f, 1.0f + __expf(-d * SIGMA_INV));
    return (face >= 0) ? s : 1.0f;
}

// R5 scheme (best measured): flat launch, 2 threads per pixel, front-batched
// 2x float4 + 2x int4 streaming loads, 1-shuffle reduce, one float4 store.
// Changes vs R5: zbuf load + store fully predicated to sub==0 lane (halves
// zbuf L1 wavefronts / issue slots), block size 128 for finer CTA granularity.
__global__ void __launch_bounds__(128)
self_shader_kernel(const float* __restrict__ zbuf,
                   const float* __restrict__ dists,
                   const int* __restrict__ pix_to_face,
                   float* __restrict__ out,
                   int n_pix) {
    int tid = blockIdx.x * blockDim.x + threadIdx.x;
    int pix = tid >> 1;     // 2 threads per pixel
    int sub = tid & 1;      // which half of K=16
    if (pix >= n_pix) return;

    size_t base = ((size_t)pix << 2) + (sub << 1);
    const float4* d4 = reinterpret_cast<const float4*>(dists) + base;
    const int4*   f4 = reinterpret_cast<const int4*>(pix_to_face) + base;

    // Front-batched streaming loads (no L2 allocate; zero reuse).
    float4 d0 = __ldcs(d4);
    float4 d1 = __ldcs(d4 + 1);
    int4   f0 = __ldcs(f4);
    int4   f1 = __ldcs(f4 + 1);

    float prod = blend_factor(d0.x, f0.x) * blend_factor(d0.y, f0.y)
               * blend_factor(d0.z, f0.z) * blend_factor(d0.w, f0.w);
    prod *= blend_factor(d1.x, f1.x) * blend_factor(d1.y, f1.y)
          * blend_factor(d1.z, f1.z) * blend_factor(d1.w, f1.w);

    // combine the two halves (lanes 2p, 2p+1 adjacent in warp)
    prod *= __shfl_xor_sync(0xFFFFFFFFu, prod, 1);

    if (sub == 0) {
        // zbuf channel 0 only: issued by half the lanes; 64B stride means two
        // pixels share a 128B line -> keep it cached (L1/L2).
        float z = __ldg(&zbuf[(size_t)pix << 4]);
        __stcs(reinterpret_cast<float4*>(out) + pix,
               make_float4(z, z, z, 1.0f - prod));
    }
}

extern "C" void kernel_launch(void* const* d_in, const int* in_sizes, int n_in,
                              void* d_out, int out_size) {
    const float* zbuf  = (const float*)d_in[0];
    const float* dists = (const float*)d_in[1];
    const int*   p2f   = (const int*)d_in[2];
    float*       out   = (float*)d_out;

    int n_pix = in_sizes[0] / 16;   // N*H*W
    long long threads_total = (long long)n_pix * 2;
    int block = 128;
    int grid = (int)((threads_total + block - 1) / block);

    self_shader_kernel<<<grid, block>>>(zbuf, dists, p2f, out, n_pix);
}

// round 16
// speedup vs baseline: 1.0420x; 1.0054x over previous
#include <cuda_runtime.h>
#include <cstdint>

#define SIGMA_INV 10000.0f  // 1 / 1e-4

// factor = 1 - prob = 1 - sigmoid(-d/sigma)*mask = mask ? sigmoid(d/sigma) : 1
__device__ __forceinline__ float blend_factor(float d, int face) {
    float s = __fdividef(1.0f, 1.0f + __expf(-d * SIGMA_INV));
    return (face >= 0) ? s : 1.0f;
}

// Best-measured scheme: flat launch, 2 threads per pixel, front-batched
// 2x float4 + 2x int4 streaming loads, 1-shuffle reduce, one float4 store.
// vs R15: the zbuf channel-0 load is hoisted into the front load batch
// (still only issued by sub==0 lanes) so all 5 LDGs are in flight before
// any math; removes exposed z-load latency ahead of the store.
__global__ void __launch_bounds__(128)
self_shader_kernel(const float* __restrict__ zbuf,
                   const float* __restrict__ dists,
                   const int* __restrict__ pix_to_face,
                   float* __restrict__ out,
                   int n_pix) {
    int tid = blockIdx.x * blockDim.x + threadIdx.x;
    int pix = tid >> 1;     // 2 threads per pixel
    int sub = tid & 1;      // which half of K=16
    if (pix >= n_pix) return;

    size_t base = ((size_t)pix << 2) + (sub << 1);
    const float4* d4 = reinterpret_cast<const float4*>(dists) + base;
    const int4*   f4 = reinterpret_cast<const int4*>(pix_to_face) + base;

    // Front-batched loads: z first (longest dependency to the store),
    // then the 4 streaming 16B loads. All issued before any math.
    float z = 0.0f;
    if (sub == 0) z = __ldg(&zbuf[(size_t)pix << 4]);  // channel 0 only
    float4 d0 = __ldcs(d4);
    float4 d1 = __ldcs(d4 + 1);
    int4   f0 = __ldcs(f4);
    int4   f1 = __ldcs(f4 + 1);

    float prod = blend_factor(d0.x, f0.x) * blend_factor(d0.y, f0.y)
               * blend_factor(d0.z, f0.z) * blend_factor(d0.w, f0.w);
    prod *= blend_factor(d1.x, f1.x) * blend_factor(d1.y, f1.y)
          * blend_factor(d1.z, f1.z) * blend_factor(d1.w, f1.w);

    // combine the two halves (lanes 2p, 2p+1 adjacent in warp)
    prod *= __shfl_xor_sync(0xFFFFFFFFu, prod, 1);

    if (sub == 0) {
        __stcs(reinterpret_cast<float4*>(out) + pix,
               make_float4(z, z, z, 1.0f - prod));
    }
}

extern "C" void kernel_launch(void* const* d_in, const int* in_sizes, int n_in,
                              void* d_out, int out_size) {
    const float* zbuf  = (const float*)d_in[0];
    const float* dists = (const float*)d_in[1];
    const int*   p2f   = (const int*)d_in[2];
    float*       out   = (float*)d_out;

    int n_pix = in_sizes[0] / 16;   // N*H*W
    long long threads_total = (long long)n_pix * 2;
    int block = 128;
    int grid = (int)((threads_total + block - 1) / block);

    self_shader_kernel<<<grid, block>>>(zbuf, dists, p2f, out, n_pix);
}